// round 4
// baseline (speedup 1.0000x reference)
#include <cuda_runtime.h>
#include <cuda_bf16.h>

// Problem constants (reference: NUM_CLASSES=5532, F=256, Q=2*NUM_CLASSES, N=131072)
#define NC    5532
#define FEAT  256
#define NV4   (FEAT / 4)     // 64 float4 per row
#define R     4              // counter striping factor
#define RCAP  32             // per-replica bucket capacity (Poisson(~6) per rep)
#define CAP   (R * RCAP)     // 128 rows per class

// Scratch (device globals; zero-initialized at load, self-resetting per call)
__device__ int4 g_cnt4[NC];          // striped per-class counts (4 replicas)
__device__ int  g_pos[NC];           // final queue row for present classes
__device__ int  g_bucket[NC * CAP];  // row indices: [class][rep][slot]
__device__ int  g_wstart;            // circular write-window start
__device__ int  g_wlen;              // window length (#present classes)
__device__ int  g_work;              // work-steal cursor for mean kernel

// ---------------------------------------------------------------------------
// 1) Count + bucket, striped: each thread handles 4 labels (int4 load); the
//    label's position mod 4 picks the counter replica -> 4x less per-address
//    contention and 4 independent atomic chains per thread.
// ---------------------------------------------------------------------------
__global__ void bucket_count_kernel(const int4* __restrict__ labels4, int N4) {
    int i = blockIdx.x * blockDim.x + threadIdx.x;
    if (i >= N4) return;
    int4 L = labels4[i];
    int base = i * 4;
    int* cnt = (int*)g_cnt4;
    int cs[4] = {L.x, L.y, L.z, L.w};
#pragma unroll
    for (int k = 0; k < 4; k++) {
        int c = cs[k];
        if (c >= 0 && c < NC) {
            int s = atomicAdd(&cnt[c * 4 + k], 1);
            if (s < RCAP) g_bucket[c * CAP + k * RCAP + s] = base + k;
        }
    }
}

// ---------------------------------------------------------------------------
// 2) Presence scan: rank among present classes -> queue position, window
//    [wstart, wstart+wlen), and reset of the work-steal cursor.
// ---------------------------------------------------------------------------
__global__ void scan_kernel(const int* __restrict__ tail_p, int Q) {
    const int CHUNK = 6;                     // ceil(5532/1024)
    int t    = threadIdx.x;
    int lane = t & 31;
    int warp = t >> 5;
    int base = t * CHUNK;

    int pres[CHUNK];
    int lp = 0;
#pragma unroll
    for (int k = 0; k < CHUNK; k++) {
        int c = base + k;
        int p = 0;
        if (c < NC) {
            int4 cv = g_cnt4[c];
            p = ((cv.x | cv.y | cv.z | cv.w) != 0) ? 1 : 0;
        }
        pres[k] = p;
        lp += p;
    }

    int ip = lp;
#pragma unroll
    for (int off = 1; off < 32; off <<= 1) {
        int v = __shfl_up_sync(0xffffffffu, ip, off);
        if (lane >= off) ip += v;
    }

    __shared__ int wp[32];
    if (lane == 31) wp[warp] = ip;
    __syncthreads();
    if (warp == 0) {
        int v = wp[lane];
#pragma unroll
        for (int off = 1; off < 32; off <<= 1) {
            int u = __shfl_up_sync(0xffffffffu, v, off);
            if (lane >= off) v += u;
        }
        wp[lane] = v;
    }
    __syncthreads();

    int tail = *tail_p;
    int ws = tail % Q; if (ws < 0) ws += Q;

    int offp = ip - lp + (warp ? wp[warp - 1] : 0);
#pragma unroll
    for (int k = 0; k < CHUNK; k++) {
        int c = base + k;
        if (c < NC && pres[k]) {
            int pos = ws + offp;
            if (pos >= Q) pos -= Q;
            g_pos[c] = pos;
            offp++;
        }
    }

    if (t == 0) {
        g_wstart = ws;
        g_wlen   = wp[31];
        g_work   = 0;        // reset work-steal cursor for mean kernel
    }
}

// ---------------------------------------------------------------------------
// 3) Init output = [queue | label], skipping rows inside the write window.
// ---------------------------------------------------------------------------
__global__ void init_out_kernel(const float4* __restrict__ queue_in,
                                const float* __restrict__ label_in,
                                float* __restrict__ out, int Q) {
    int nq4 = Q * NV4;
    int i = blockIdx.x * blockDim.x + threadIdx.x;
    int ws = g_wstart, wl = g_wlen;

    if (i < nq4) {
        int row = i >> 6;                 // NV4 = 64
        int d = row - ws; if (d < 0) d += Q;
        if (d >= wl) ((float4*)out)[i] = queue_in[i];
    } else {
        int j = i - nq4;
        if (j < Q) {
            int d = j - ws; if (d < 0) d += Q;
            if (d >= wl) out[(size_t)Q * FEAT + j] = label_in[j];
        }
    }
}

// ---------------------------------------------------------------------------
// 4) Gather + mean + scatter: persistent one-wave grid (64-thread blocks),
//    classes dispensed by a work-steal counter for perfect balance.
//    Register accumulation, 8-row unroll, streaming loads. Self-resets
//    g_cnt4. Generic rescan fallback on replica overflow (never taken).
// ---------------------------------------------------------------------------
__global__ void __launch_bounds__(64) mean_kernel(
        const float4* __restrict__ feat,
        const int* __restrict__ labels, int N,
        float* __restrict__ out, int Q) {
    __shared__ int  sidx[CAP];
    __shared__ int  s_c;
    __shared__ int4 s_cv;
    int t = threadIdx.x;

    for (;;) {
        if (t == 0) {
            s_c = atomicAdd(&g_work, 1);
            if (s_c < NC) {
                s_cv = g_cnt4[s_c];
                g_cnt4[s_c] = make_int4(0, 0, 0, 0);   // self-reset
            }
        }
        __syncthreads();
        int c = s_c;
        if (c >= NC) return;
        int4 cv = s_cv;
        __syncthreads();          // sidx/s_c reuse guard

        int cnt = cv.x + cv.y + cv.z + cv.w;
        if (cnt == 0) continue;

        int pos = g_pos[c];
        float4 acc = make_float4(0.f, 0.f, 0.f, 0.f);
        bool ovf = (cv.x > RCAP) | (cv.y > RCAP) | (cv.z > RCAP) | (cv.w > RCAP);

        if (!ovf) {
            // compact the 4 replica segments into smem
            int cr[4] = {cv.x, cv.y, cv.z, cv.w};
            int off = 0;
#pragma unroll
            for (int r = 0; r < 4; r++) {
                if (t < cr[r]) sidx[off + t] = g_bucket[c * CAP + r * RCAP + t];
                off += cr[r];
            }
            __syncthreads();

            int r = 0;
            for (; r + 8 <= cnt; r += 8) {
                float4 v0 = __ldcs(feat + (size_t)sidx[r + 0] * NV4 + t);
                float4 v1 = __ldcs(feat + (size_t)sidx[r + 1] * NV4 + t);
                float4 v2 = __ldcs(feat + (size_t)sidx[r + 2] * NV4 + t);
                float4 v3 = __ldcs(feat + (size_t)sidx[r + 3] * NV4 + t);
                float4 v4 = __ldcs(feat + (size_t)sidx[r + 4] * NV4 + t);
                float4 v5 = __ldcs(feat + (size_t)sidx[r + 5] * NV4 + t);
                float4 v6 = __ldcs(feat + (size_t)sidx[r + 6] * NV4 + t);
                float4 v7 = __ldcs(feat + (size_t)sidx[r + 7] * NV4 + t);
                acc.x += (v0.x + v1.x) + (v2.x + v3.x) + (v4.x + v5.x) + (v6.x + v7.x);
                acc.y += (v0.y + v1.y) + (v2.y + v3.y) + (v4.y + v5.y) + (v6.y + v7.y);
                acc.z += (v0.z + v1.z) + (v2.z + v3.z) + (v4.z + v5.z) + (v6.z + v7.z);
                acc.w += (v0.w + v1.w) + (v2.w + v3.w) + (v4.w + v5.w) + (v6.w + v7.w);
            }
            for (; r < cnt; r++) {
                float4 v = __ldcs(feat + (size_t)sidx[r] * NV4 + t);
                acc.x += v.x; acc.y += v.y; acc.z += v.z; acc.w += v.w;
            }
        } else {
            // Generic fallback: rescan all labels (correct for any input).
            for (int i = 0; i < N; i++) {
                if (__ldg(&labels[i]) == c) {
                    float4 v = __ldcs(feat + (size_t)i * NV4 + t);
                    acc.x += v.x; acc.y += v.y; acc.z += v.z; acc.w += v.w;
                }
            }
        }

        float inv = 1.0f / (float)cnt;
        float4 o = make_float4(acc.x * inv, acc.y * inv, acc.z * inv, acc.w * inv);
        ((float4*)out)[(size_t)pos * NV4 + t] = o;
        if (t == 0) out[(size_t)Q * FEAT + pos] = (float)c;
        __syncthreads();          // done with sidx before next steal
    }
}

// ---------------------------------------------------------------------------
// Launch.  Inputs: features f32[N,256], pid_labels i32[N],
//   large_batch_queue f32[Q,256], queue_label f32[Q], tail i32[1]
// Output: [new_queue f32[Q,256] | new_label f32[Q]]
// ---------------------------------------------------------------------------
extern "C" void kernel_launch(void* const* d_in, const int* in_sizes, int n_in,
                              void* d_out, int out_size) {
    const float4* feat    = (const float4*)d_in[0];
    const int*    labels  = (const int*)d_in[1];
    const float4* queue0  = (const float4*)d_in[2];
    const float*  qlabel0 = (const float*)d_in[3];
    const int*    tail_p  = (const int*)d_in[4];

    int N = in_sizes[1];              // 131072 (divisible by 4)
    int Q = in_sizes[3];              // 11064
    float* out = (float*)d_out;

    // 1) striped count + bucket
    {
        int N4 = N / 4;
        int threads = 256;
        int blocks = (N4 + threads - 1) / threads;
        bucket_count_kernel<<<blocks, threads>>>((const int4*)labels, N4);
    }
    // 2) presence scan -> positions, window, work cursor
    scan_kernel<<<1, 1024>>>(tail_p, Q);
    // 3) init output outside the write window
    {
        int total = Q * NV4 + Q;
        int threads = 256;
        int blocks = (total + threads - 1) / threads;
        init_out_kernel<<<blocks, threads>>>(queue0, qlabel0, out, Q);
    }
    // 4) persistent one-wave gather/mean/scatter with work stealing
    mean_kernel<<<148 * 32, 64>>>(feat, labels, N, out, Q);
}

// round 6
// speedup vs baseline: 1.1003x; 1.1003x over previous
#include <cuda_runtime.h>
#include <cuda_bf16.h>

// Problem constants (reference: NUM_CLASSES=5532, F=256, Q=2*NUM_CLASSES, N=131072)
#define NC    5532
#define FEAT  256
#define NV4   (FEAT / 4)     // 64 float4 per row
#define R     4              // counter striping factor
#define RCAP  32             // per-replica bucket capacity
#define CAP   (R * RCAP)     // 128 rows per class
#define CPB   2              // classes per block (static), single-wave grid

// Scratch (device globals; zero-initialized at load, self-resetting per call)
__device__ int4 g_cnt4[NC];          // striped per-class counts (4 replicas)
__device__ int  g_pos[NC];           // final queue row for present classes
__device__ int  g_bucket[NC * CAP];  // row indices: [class][rep][slot]
__device__ int  g_wstart;            // circular write-window start
__device__ int  g_wlen;              // window length (#present classes)

// ---------------------------------------------------------------------------
// 1) Count + bucket, striped: 4 labels per thread (int4); label position
//    mod 4 picks the counter replica -> 4x less per-address contention.
// ---------------------------------------------------------------------------
__global__ void bucket_count_kernel(const int4* __restrict__ labels4, int N4) {
    int i = blockIdx.x * blockDim.x + threadIdx.x;
    if (i >= N4) return;
    int4 L = labels4[i];
    int base = i * 4;
    int* cnt = (int*)g_cnt4;
    int cs[4] = {L.x, L.y, L.z, L.w};
#pragma unroll
    for (int k = 0; k < 4; k++) {
        int c = cs[k];
        if (c >= 0 && c < NC) {
            int s = atomicAdd(&cnt[c * 4 + k], 1);
            if (s < RCAP) g_bucket[c * CAP + k * RCAP + s] = base + k;
        }
    }
}

// ---------------------------------------------------------------------------
// 2) Presence scan: rank among present classes -> queue position + window.
// ---------------------------------------------------------------------------
__global__ void scan_kernel(const int* __restrict__ tail_p, int Q) {
    const int CHUNK = 6;                     // ceil(5532/1024)
    int t    = threadIdx.x;
    int lane = t & 31;
    int warp = t >> 5;
    int base = t * CHUNK;

    int pres[CHUNK];
    int lp = 0;
#pragma unroll
    for (int k = 0; k < CHUNK; k++) {
        int c = base + k;
        int p = 0;
        if (c < NC) {
            int4 cv = g_cnt4[c];
            p = ((cv.x | cv.y | cv.z | cv.w) != 0) ? 1 : 0;
        }
        pres[k] = p;
        lp += p;
    }

    int ip = lp;
#pragma unroll
    for (int off = 1; off < 32; off <<= 1) {
        int v = __shfl_up_sync(0xffffffffu, ip, off);
        if (lane >= off) ip += v;
    }

    __shared__ int wp[32];
    if (lane == 31) wp[warp] = ip;
    __syncthreads();
    if (warp == 0) {
        int v = wp[lane];
#pragma unroll
        for (int off = 1; off < 32; off <<= 1) {
            int u = __shfl_up_sync(0xffffffffu, v, off);
            if (lane >= off) v += u;
        }
        wp[lane] = v;
    }
    __syncthreads();

    int tail = *tail_p;
    int ws = tail % Q; if (ws < 0) ws += Q;

    int offp = ip - lp + (warp ? wp[warp - 1] : 0);
#pragma unroll
    for (int k = 0; k < CHUNK; k++) {
        int c = base + k;
        if (c < NC && pres[k]) {
            int pos = ws + offp;
            if (pos >= Q) pos -= Q;
            g_pos[c] = pos;
            offp++;
        }
    }

    if (t == 0) {
        g_wstart = ws;
        g_wlen   = wp[31];
    }
}

// ---------------------------------------------------------------------------
// 3) Init output = [queue | label], skipping rows inside the write window.
// ---------------------------------------------------------------------------
__global__ void init_out_kernel(const float4* __restrict__ queue_in,
                                const float* __restrict__ label_in,
                                float* __restrict__ out, int Q) {
    int nq4 = Q * NV4;
    int i = blockIdx.x * blockDim.x + threadIdx.x;
    int ws = g_wstart, wl = g_wlen;

    if (i < nq4) {
        int row = i >> 6;                 // NV4 = 64
        int d = row - ws; if (d < 0) d += Q;
        if (d >= wl) ((float4*)out)[i] = queue_in[i];
    } else {
        int j = i - nq4;
        if (j < Q) {
            int d = j - ws; if (d < 0) d += Q;
            if (d >= wl) out[(size_t)Q * FEAT + j] = label_in[j];
        }
    }
}

// ---------------------------------------------------------------------------
// 4) Gather + mean + scatter: STATIC single-wave grid. Block b handles
//    classes 2b and 2b+1. Count is read+reset by thread 0 ONLY and
//    broadcast through shared memory (fixes the R5 read/reset race and
//    makes all branches block-uniform). Double-buffered sidx.
// ---------------------------------------------------------------------------
__global__ void __launch_bounds__(64) mean_kernel(
        const float4* __restrict__ feat,
        const int* __restrict__ labels, int N,
        float* __restrict__ out, int Q) {
    __shared__ int  sidx[CPB][CAP];
    __shared__ int4 s_cv[CPB];
    int t = threadIdx.x;

#pragma unroll
    for (int s = 0; s < CPB; s++) {
        int c = blockIdx.x * CPB + s;
        if (c >= NC) return;     // NC even, CPB=2: uniform across the block

        // Thread 0 alone reads AND resets the counter; broadcast via smem.
        if (t == 0) {
            s_cv[s] = g_cnt4[c];
            g_cnt4[c] = make_int4(0, 0, 0, 0);
        }
        __syncthreads();
        int4 cv = s_cv[s];       // uniform
        int cnt = cv.x + cv.y + cv.z + cv.w;
        if (cnt == 0) continue;  // uniform branch

        int pos = g_pos[c];
        float4 acc = make_float4(0.f, 0.f, 0.f, 0.f);
        bool ovf = (cv.x > RCAP) | (cv.y > RCAP) | (cv.z > RCAP) | (cv.w > RCAP);

        if (!ovf) {
            // compact the 4 replica segments into this class's sidx buffer
            int cr[4] = {cv.x, cv.y, cv.z, cv.w};
            int off = 0;
#pragma unroll
            for (int r = 0; r < 4; r++) {
                if (t < cr[r]) sidx[s][off + t] = g_bucket[c * CAP + r * RCAP + t];
                off += cr[r];
            }
            __syncthreads();

            int r = 0;
            for (; r + 8 <= cnt; r += 8) {
                float4 v0 = __ldcs(feat + (size_t)sidx[s][r + 0] * NV4 + t);
                float4 v1 = __ldcs(feat + (size_t)sidx[s][r + 1] * NV4 + t);
                float4 v2 = __ldcs(feat + (size_t)sidx[s][r + 2] * NV4 + t);
                float4 v3 = __ldcs(feat + (size_t)sidx[s][r + 3] * NV4 + t);
                float4 v4 = __ldcs(feat + (size_t)sidx[s][r + 4] * NV4 + t);
                float4 v5 = __ldcs(feat + (size_t)sidx[s][r + 5] * NV4 + t);
                float4 v6 = __ldcs(feat + (size_t)sidx[s][r + 6] * NV4 + t);
                float4 v7 = __ldcs(feat + (size_t)sidx[s][r + 7] * NV4 + t);
                acc.x += (v0.x + v1.x) + (v2.x + v3.x) + (v4.x + v5.x) + (v6.x + v7.x);
                acc.y += (v0.y + v1.y) + (v2.y + v3.y) + (v4.y + v5.y) + (v6.y + v7.y);
                acc.z += (v0.z + v1.z) + (v2.z + v3.z) + (v4.z + v5.z) + (v6.z + v7.z);
                acc.w += (v0.w + v1.w) + (v2.w + v3.w) + (v4.w + v5.w) + (v6.w + v7.w);
            }
            for (; r < cnt; r++) {
                float4 v = __ldcs(feat + (size_t)sidx[s][r] * NV4 + t);
                acc.x += v.x; acc.y += v.y; acc.z += v.z; acc.w += v.w;
            }
        } else {
            // Generic fallback: rescan all labels (correct for any input).
            for (int i = 0; i < N; i++) {
                if (__ldg(&labels[i]) == c) {
                    float4 v = __ldcs(feat + (size_t)i * NV4 + t);
                    acc.x += v.x; acc.y += v.y; acc.z += v.z; acc.w += v.w;
                }
            }
        }

        float inv = 1.0f / (float)cnt;
        float4 o = make_float4(acc.x * inv, acc.y * inv, acc.z * inv, acc.w * inv);
        ((float4*)out)[(size_t)pos * NV4 + t] = o;
        if (t == 0) out[(size_t)Q * FEAT + pos] = (float)c;
    }
}

// ---------------------------------------------------------------------------
// Launch.  Inputs: features f32[N,256], pid_labels i32[N],
//   large_batch_queue f32[Q,256], queue_label f32[Q], tail i32[1]
// Output: [new_queue f32[Q,256] | new_label f32[Q]]
// ---------------------------------------------------------------------------
extern "C" void kernel_launch(void* const* d_in, const int* in_sizes, int n_in,
                              void* d_out, int out_size) {
    const float4* feat    = (const float4*)d_in[0];
    const int*    labels  = (const int*)d_in[1];
    const float4* queue0  = (const float4*)d_in[2];
    const float*  qlabel0 = (const float*)d_in[3];
    const int*    tail_p  = (const int*)d_in[4];

    int N = in_sizes[1];              // 131072 (divisible by 4)
    int Q = in_sizes[3];              // 11064
    float* out = (float*)d_out;

    // 1) striped count + bucket
    {
        int N4 = N / 4;
        int threads = 256;
        int blocks = (N4 + threads - 1) / threads;
        bucket_count_kernel<<<blocks, threads>>>((const int4*)labels, N4);
    }
    // 2) presence scan -> positions + window
    scan_kernel<<<1, 1024>>>(tail_p, Q);
    // 3) init output outside the write window
    {
        int total = Q * NV4 + Q;
        int threads = 256;
        int blocks = (total + threads - 1) / threads;
        init_out_kernel<<<blocks, threads>>>(queue0, qlabel0, out, Q);
    }
    // 4) single-wave static gather/mean/scatter
    {
        int blocks = (NC + CPB - 1) / CPB;   // 2766 < 4736 (one wave)
        mean_kernel<<<blocks, 64>>>(feat, labels, N, out, Q);
    }
}

// round 7
// speedup vs baseline: 1.2456x; 1.1320x over previous
#include <cuda_runtime.h>
#include <cuda_bf16.h>

// Problem constants (reference: NUM_CLASSES=5532, F=256, Q=2*NUM_CLASSES, N=131072)
#define NC    5532
#define FEAT  256
#define NV4   (FEAT / 4)     // 64 float4 per row
#define RCAP  32             // per-replica bucket capacity (Poisson(~6)/replica)
#define CAP   (4 * RCAP)     // 128 rows per class
#define PREP_BUCKET_BLOCKS 512
#define PREP_COPY_BLOCKS   1536

// Scratch (device globals; zero-initialized at load, self-resetting per call)
__device__ int4 g_cnt4[NC];          // striped per-class counts (4 replicas)
__device__ int  g_pos[NC];           // final queue row for present classes
__device__ int  g_bucket[NC * CAP];  // row indices: [class][replica][slot]

// ---------------------------------------------------------------------------
// 1) PREP (fused): blocks [0,512) do striped count+bucket (1 label/thread,
//    replica = i&3 -> 6-way instead of 24-way per-address contention);
//    blocks [512,2048) copy the full output (queue + labels) grid-stride.
//    The bandwidth-bound copy overlaps the latency-bound atomic ticketing.
// ---------------------------------------------------------------------------
__global__ void prep_kernel(const int* __restrict__ labels, int N,
                            const float4* __restrict__ queue_in,
                            const float4* __restrict__ label_in,
                            float4* __restrict__ out4,
                            int nq4, int nl4) {
    if (blockIdx.x < PREP_BUCKET_BLOCKS) {
        int i = blockIdx.x * blockDim.x + threadIdx.x;
        if (i < N) {
            int c = labels[i];
            if (c >= 0 && c < NC) {
                int r = i & 3;
                int s = atomicAdd(&((int*)g_cnt4)[c * 4 + r], 1);
                if (s < RCAP) g_bucket[c * CAP + r * RCAP + s] = i;
            }
        }
    } else {
        int total = nq4 + nl4;
        int stride = (gridDim.x - PREP_BUCKET_BLOCKS) * blockDim.x;
        for (int i = (blockIdx.x - PREP_BUCKET_BLOCKS) * blockDim.x + threadIdx.x;
             i < total; i += stride) {
            out4[i] = (i < nq4) ? queue_in[i] : label_in[i - nq4];
        }
    }
}

// ---------------------------------------------------------------------------
// 2) Presence scan: rank among present classes -> circular queue position.
// ---------------------------------------------------------------------------
__global__ void scan_kernel(const int* __restrict__ tail_p, int Q) {
    const int CHUNK = 6;                     // ceil(5532/1024)
    int t    = threadIdx.x;
    int lane = t & 31;
    int warp = t >> 5;
    int base = t * CHUNK;

    int pres[CHUNK];
    int lp = 0;
#pragma unroll
    for (int k = 0; k < CHUNK; k++) {
        int c = base + k;
        int p = 0;
        if (c < NC) {
            int4 cv = g_cnt4[c];
            p = ((cv.x | cv.y | cv.z | cv.w) != 0) ? 1 : 0;
        }
        pres[k] = p;
        lp += p;
    }

    int ip = lp;
#pragma unroll
    for (int off = 1; off < 32; off <<= 1) {
        int v = __shfl_up_sync(0xffffffffu, ip, off);
        if (lane >= off) ip += v;
    }

    __shared__ int wp[32];
    if (lane == 31) wp[warp] = ip;
    __syncthreads();
    if (warp == 0) {
        int v = wp[lane];
#pragma unroll
        for (int off = 1; off < 32; off <<= 1) {
            int u = __shfl_up_sync(0xffffffffu, v, off);
            if (lane >= off) v += u;
        }
        wp[lane] = v;
    }
    __syncthreads();

    int tail = *tail_p;
    int ws = tail % Q; if (ws < 0) ws += Q;

    int offp = ip - lp + (warp ? wp[warp - 1] : 0);
#pragma unroll
    for (int k = 0; k < CHUNK; k++) {
        int c = base + k;
        if (c < NC && pres[k]) {
            int pos = ws + offp;
            if (pos >= Q) pos -= Q;
            g_pos[c] = pos;
            offp++;
        }
    }
}

// ---------------------------------------------------------------------------
// 3) Mean: one block (2 warps) per class. The two warps split the row list;
//    each lane owns 2 float4 columns (lane, lane+32) so ONE warp reads a full
//    1KB row with 2 LDG.128 per lane. 2-row batches keep live registers low
//    (~36-40) -> ~50+ resident warps/SM. Cross-warp reduce via smem.
//    Thread 0 reads+resets the striped count (race-free smem broadcast).
// ---------------------------------------------------------------------------
__global__ void __launch_bounds__(64) mean_kernel(
        const float4* __restrict__ feat,
        const int* __restrict__ labels, int N,
        float* __restrict__ out, int Q) {
    __shared__ int    sidx[CAP];
    __shared__ int4   s_cv;
    __shared__ float4 s_part[64];

    int t    = threadIdx.x;
    int lane = t & 31;
    int w    = t >> 5;
    int c    = blockIdx.x;

    if (t == 0) {
        s_cv = g_cnt4[c];
        g_cnt4[c] = make_int4(0, 0, 0, 0);   // self-reset for next call
    }
    __syncthreads();
    int4 cv = s_cv;                          // uniform
    int cnt = cv.x + cv.y + cv.z + cv.w;
    if (cnt == 0) return;                    // uniform

    int pos = g_pos[c];
    float4 a0 = make_float4(0.f, 0.f, 0.f, 0.f);
    float4 a1 = make_float4(0.f, 0.f, 0.f, 0.f);
    bool ovf = (cv.x > RCAP) | (cv.y > RCAP) | (cv.z > RCAP) | (cv.w > RCAP);

    if (!ovf) {
        // compact the 4 replica segments into smem (cnt <= 128)
        int cr[4] = {cv.x, cv.y, cv.z, cv.w};
        int off = 0;
#pragma unroll
        for (int r = 0; r < 4; r++) {
            if (t < cr[r]) sidx[off + t] = g_bucket[c * CAP + r * RCAP + t];
            off += cr[r];
        }
        __syncthreads();

        // split rows between the two warps
        int half = (cnt + 1) >> 1;
        int beg = w ? half : 0;
        int end = w ? cnt  : half;

        int r = beg;
        for (; r + 2 <= end; r += 2) {
            const float4* p0 = feat + (size_t)sidx[r]     * NV4;
            const float4* p1 = feat + (size_t)sidx[r + 1] * NV4;
            float4 u0 = __ldcs(p0 + lane);
            float4 u1 = __ldcs(p0 + lane + 32);
            float4 v0 = __ldcs(p1 + lane);
            float4 v1 = __ldcs(p1 + lane + 32);
            a0.x += u0.x + v0.x;  a0.y += u0.y + v0.y;
            a0.z += u0.z + v0.z;  a0.w += u0.w + v0.w;
            a1.x += u1.x + v1.x;  a1.y += u1.y + v1.y;
            a1.z += u1.z + v1.z;  a1.w += u1.w + v1.w;
        }
        if (r < end) {
            const float4* p0 = feat + (size_t)sidx[r] * NV4;
            float4 u0 = __ldcs(p0 + lane);
            float4 u1 = __ldcs(p0 + lane + 32);
            a0.x += u0.x; a0.y += u0.y; a0.z += u0.z; a0.w += u0.w;
            a1.x += u1.x; a1.y += u1.y; a1.z += u1.z; a1.w += u1.w;
        }
    } else {
        // Generic fallback (never taken for this distribution): warp w scans
        // its half of the label array.
        int beg = w * (N >> 1);
        int end = beg + (N >> 1);
        for (int i = beg; i < end; i++) {
            if (__ldg(&labels[i]) == c) {
                const float4* p = feat + (size_t)i * NV4;
                float4 u0 = __ldcs(p + lane);
                float4 u1 = __ldcs(p + lane + 32);
                a0.x += u0.x; a0.y += u0.y; a0.z += u0.z; a0.w += u0.w;
                a1.x += u1.x; a1.y += u1.y; a1.z += u1.z; a1.w += u1.w;
            }
        }
    }

    // cross-warp reduce
    if (w == 1) { s_part[lane] = a0; s_part[32 + lane] = a1; }
    __syncthreads();
    if (w == 0) {
        float4 b0 = s_part[lane], b1 = s_part[32 + lane];
        a0.x += b0.x; a0.y += b0.y; a0.z += b0.z; a0.w += b0.w;
        a1.x += b1.x; a1.y += b1.y; a1.z += b1.z; a1.w += b1.w;
        float inv = 1.0f / (float)cnt;
        a0.x *= inv; a0.y *= inv; a0.z *= inv; a0.w *= inv;
        a1.x *= inv; a1.y *= inv; a1.z *= inv; a1.w *= inv;
        float4* oq = (float4*)out;
        oq[(size_t)pos * NV4 + lane]      = a0;
        oq[(size_t)pos * NV4 + lane + 32] = a1;
        if (lane == 0) out[(size_t)Q * FEAT + pos] = (float)c;
    }
}

// ---------------------------------------------------------------------------
// Launch.  Inputs: features f32[N,256], pid_labels i32[N],
//   large_batch_queue f32[Q,256], queue_label f32[Q], tail i32[1]
// Output: [new_queue f32[Q,256] | new_label f32[Q]]
// ---------------------------------------------------------------------------
extern "C" void kernel_launch(void* const* d_in, const int* in_sizes, int n_in,
                              void* d_out, int out_size) {
    const float4* feat    = (const float4*)d_in[0];
    const int*    labels  = (const int*)d_in[1];
    const float4* queue0  = (const float4*)d_in[2];
    const float4* qlabel0 = (const float4*)d_in[3];
    const int*    tail_p  = (const int*)d_in[4];

    int N = in_sizes[1];              // 131072
    int Q = in_sizes[3];              // 11064 (divisible by 4)
    float* out = (float*)d_out;

    // 1) fused bucket+count and full output copy
    {
        int nq4 = Q * NV4;
        int nl4 = Q / 4;
        prep_kernel<<<PREP_BUCKET_BLOCKS + PREP_COPY_BLOCKS, 256>>>(
            labels, N, queue0, qlabel0, (float4*)out, nq4, nl4);
    }
    // 2) presence scan -> queue positions
    scan_kernel<<<1, 1024>>>(tail_p, Q);
    // 3) gather + mean + scatter (2 warps per class, high residency)
    mean_kernel<<<NC, 64>>>(feat, labels, N, out, Q);
}